// round 4
// baseline (speedup 1.0000x reference)
#include <cuda_runtime.h>
#include <stdint.h>

// PluginEmbedding: sparse embedding lookup + per-row sum combine.
// Inputs (metadata order):
//   d_in[0] table         float32 [1000000, 128]
//   d_in[1] row_offsets   int32   [212993]   (JAX default x64=off downcasts int64->int32)
//   d_in[2] value_tensors int32   [212992]
//   d_in[3] nnz_array     int32   scalar (unused)
//   d_in[4] output_shape  int32   [3]    (unused)
// Output: float32 [8192, 26, 128] = [212992, 128]
//
// out[r] = sum_{j in [off[r], off[r+1])} table[val[j]]   (setup: exactly 1 nnz/row)
// One warp per row; lane l owns float4 l of the 512B row. Pure HBM-bound gather.
// Index clamped to table bounds: if the dtype assumption is ever wrong we get a
// clean rel_err failure (with ncu evidence) instead of an illegal access.

static constexpr int  kVec     = 128;          // floats per row
static constexpr int  kVocab   = 1000000;
static constexpr long kNumRows = 8192L * 26L;  // 212992

__global__ __launch_bounds__(256) void pe_gather_kernel(
    const float* __restrict__ table,
    const int*   __restrict__ row_offsets,
    const int*   __restrict__ vals,
    float*       __restrict__ out)
{
    const long long warp = ((long long)blockIdx.x * blockDim.x + threadIdx.x) >> 5;
    const int lane = threadIdx.x & 31;
    if (warp >= kNumRows) return;

    // Offsets are a tiny sequential stream; redundant per-lane loads hit L1/L2.
    const int beg = __ldg(&row_offsets[warp]);
    const int end = __ldg(&row_offsets[warp + 1]);

    float4 acc = make_float4(0.f, 0.f, 0.f, 0.f);
    for (int j = beg; j < end; ++j) {
        int idx = __ldg(&vals[j]);
        // Defensive clamp: never fault, surface dtype errors as rel_err instead.
        idx = min(max(idx, 0), kVocab - 1);
        const float4* src =
            reinterpret_cast<const float4*>(table + (long long)idx * kVec) + lane;
        const float4 v = __ldg(src);
        acc.x += v.x; acc.y += v.y; acc.z += v.z; acc.w += v.w;
    }

    reinterpret_cast<float4*>(out + warp * (long long)kVec)[lane] = acc;
}

extern "C" void kernel_launch(void* const* d_in, const int* in_sizes, int n_in,
                              void* d_out, int out_size)
{
    const float* table = (const float*)d_in[0];
    const int*   offs  = (const int*)d_in[1];
    const int*   vals  = (const int*)d_in[2];
    float*       out   = (float*)d_out;

    (void)in_sizes; (void)n_in; (void)out_size;

    const long long total_threads = kNumRows * 32LL;   // 1 warp per row
    const int block = 256;
    const long long grid = (total_threads + block - 1) / block; // 26624

    pe_gather_kernel<<<(unsigned)grid, block>>>(table, offs, vals, out);
}

// round 5
// speedup vs baseline: 1.4253x; 1.4253x over previous
#include <cuda_runtime.h>
#include <stdint.h>

// PluginEmbedding: sparse embedding lookup + per-row sum combine.
//   d_in[0] table         float32 [1000000, 128]
//   d_in[1] row_offsets   int32   [212993]
//   d_in[2] value_tensors int32   [212992]
//   d_in[3,4] unused
// Output: float32 [212992, 128]
//
// R4 analysis: latency-bound (DRAM 42%, 1 outstanding table load per warp).
// This version: 4 rows per warp -> 4 independent gather chains front-batched
// (4x MLP), streaming stores to keep output out of L2 (preserve table reuse).

static constexpr int  kVec        = 128;          // floats per row
static constexpr int  kVocab      = 1000000;
static constexpr long kNumRows    = 8192L * 26L;  // 212992
static constexpr int  kRowsPerWarp = 4;

__global__ __launch_bounds__(256) void pe_gather_kernel(
    const float* __restrict__ table,
    const int*   __restrict__ row_offsets,
    const int*   __restrict__ vals,
    float*       __restrict__ out)
{
    const long long warp = ((long long)blockIdx.x * blockDim.x + threadIdx.x) >> 5;
    const int lane = threadIdx.x & 31;
    const long long r0 = warp * kRowsPerWarp;
    if (r0 >= kNumRows) return;

    // 1) Batch the offset loads (sequential stream, L1/L2 hits).
    int begs[kRowsPerWarp], ends[kRowsPerWarp];
#pragma unroll
    for (int u = 0; u < kRowsPerWarp; ++u) {
        begs[u] = __ldg(&row_offsets[r0 + u]);
        ends[u] = __ldg(&row_offsets[r0 + u + 1]);
    }

    // 2) Batch the index loads for the first entry of each row.
    int idx[kRowsPerWarp];
#pragma unroll
    for (int u = 0; u < kRowsPerWarp; ++u) {
        idx[u] = (begs[u] < ends[u]) ? __ldg(&vals[begs[u]]) : -1;
    }

    // 3) Batch the 4 independent 512B table gathers (the MLP that matters).
    float4 acc[kRowsPerWarp];
#pragma unroll
    for (int u = 0; u < kRowsPerWarp; ++u) {
        if (idx[u] >= 0) {
            int i = min(idx[u], kVocab - 1);   // defensive clamp
            acc[u] = __ldg(reinterpret_cast<const float4*>(
                         table + (long long)i * kVec) + lane);
        } else {
            acc[u] = make_float4(0.f, 0.f, 0.f, 0.f);
        }
    }

    // 4) Generic tail: additional entries per row (none in this dataset).
#pragma unroll
    for (int u = 0; u < kRowsPerWarp; ++u) {
        for (int j = begs[u] + 1; j < ends[u]; ++j) {
            int i = __ldg(&vals[j]);
            i = min(max(i, 0), kVocab - 1);
            const float4 v = __ldg(reinterpret_cast<const float4*>(
                                 table + (long long)i * kVec) + lane);
            acc[u].x += v.x; acc[u].y += v.y; acc[u].z += v.z; acc[u].w += v.w;
        }
    }

    // 5) Streaming stores: output never re-read, keep it out of L2.
#pragma unroll
    for (int u = 0; u < kRowsPerWarp; ++u) {
        __stcs(reinterpret_cast<float4*>(out + (r0 + u) * (long long)kVec) + lane,
               acc[u]);
    }
}

extern "C" void kernel_launch(void* const* d_in, const int* in_sizes, int n_in,
                              void* d_out, int out_size)
{
    const float* table = (const float*)d_in[0];
    const int*   offs  = (const int*)d_in[1];
    const int*   vals  = (const int*)d_in[2];
    float*       out   = (float*)d_out;

    (void)in_sizes; (void)n_in; (void)out_size;

    const long long n_warps = (kNumRows + kRowsPerWarp - 1) / kRowsPerWarp; // 53248
    const int block = 256;                    // 8 warps/block
    const long long grid = (n_warps * 32 + block - 1) / block;              // 6656

    pe_gather_kernel<<<(unsigned)grid, block>>>(table, offs, vals, out);
}